// round 1
// baseline (speedup 1.0000x reference)
#include <cuda_runtime.h>
#include <math.h>

// Problem constants
#define Bb 16
#define Gg 512
#define Pp 512
#define Ee 256
#define Hh 16
#define Kd 16
#define HK 256

// Scratch (device globals: allocation-free rule)
__device__ float g_c1[Bb * HK];                 // input1 @ Wq[0:E]
__device__ float g_Kt[Bb * Hh * Pp * Kd];       // [B,H,P,Kd]
__device__ float g_Vt[Bb * Hh * Pp * Kd];       // [B,H,P,Kd]
__device__ float g_Qt[Bb * Hh * Gg * Kd];       // [B,H,G,Kd]
__device__ float g_attn[Bb * Gg * HK];          // [B,G,H*Kd]
__device__ float g_mh[Bb * Gg * HK];            // [B,G,E]
__device__ float g_s2[Bb * Gg * Pp];            // clipped scores

// ---------------------------------------------------------------------------
// c1[b][n] = sum_e input1[b,e] * Wq[e, n]
// ---------------------------------------------------------------------------
__global__ void qbias_kernel(const float* __restrict__ input1,
                             const float* __restrict__ Wq) {
    int b = blockIdx.x;
    int n = threadIdx.x;
    const float* x = input1 + b * Ee;
    float acc = 0.f;
#pragma unroll 4
    for (int e = 0; e < Ee; e++) acc += x[e] * Wq[e * HK + n];
    g_c1[b * HK + n] = acc;
}

// ---------------------------------------------------------------------------
// Generic tiled fp32 GEMM: C[8192,256] = A[8192,256] @ W[256,256]
// mode 0: write heads layout [B,H,512,16]           (K / V)
// mode 1: heads layout + c1[b] + t[m]*wq_last       (Q)
// mode 2: flat [m,256] + bias[n]                    (Wc)
// 64x64 tile, 256 threads, 4x4 per thread, BK=16
// ---------------------------------------------------------------------------
__global__ __launch_bounds__(256)
void gemm_kernel(const float* __restrict__ A, const float* __restrict__ W,
                 float* __restrict__ Cout, int mode,
                 const float* __restrict__ tvec,
                 const float* __restrict__ wq_last,
                 const float* __restrict__ bias) {
    __shared__ float As[16][68];   // transposed A tile: As[k][m]
    __shared__ float Bs[16][68];   // natural B tile:    Bs[k][n]
    const int tid = threadIdx.x;
    const int m0 = blockIdx.x * 64, n0 = blockIdx.y * 64;
    const int tx = tid & 15, ty = tid >> 4;

    float acc[4][4];
#pragma unroll
    for (int i = 0; i < 4; i++)
#pragma unroll
        for (int j = 0; j < 4; j++) acc[i][j] = 0.f;

    const int ar = tid >> 2, ac4 = (tid & 3) * 4;
    const int bkr = tid >> 4, bc4 = (tid & 15) * 4;

    for (int k0 = 0; k0 < 256; k0 += 16) {
        float4 av = *reinterpret_cast<const float4*>(A + (m0 + ar) * 256 + k0 + ac4);
        float4 bv = *reinterpret_cast<const float4*>(W + (k0 + bkr) * 256 + n0 + bc4);
        As[ac4 + 0][ar] = av.x;
        As[ac4 + 1][ar] = av.y;
        As[ac4 + 2][ar] = av.z;
        As[ac4 + 3][ar] = av.w;
        *reinterpret_cast<float4*>(&Bs[bkr][bc4]) = bv;
        __syncthreads();
#pragma unroll
        for (int kk = 0; kk < 16; kk++) {
            float4 a4 = *reinterpret_cast<const float4*>(&As[kk][ty * 4]);
            float4 b4 = *reinterpret_cast<const float4*>(&Bs[kk][tx * 4]);
            float aa[4] = {a4.x, a4.y, a4.z, a4.w};
            float bb[4] = {b4.x, b4.y, b4.z, b4.w};
#pragma unroll
            for (int i = 0; i < 4; i++)
#pragma unroll
                for (int j = 0; j < 4; j++) acc[i][j] += aa[i] * bb[j];
        }
        __syncthreads();
    }

#pragma unroll
    for (int i = 0; i < 4; i++) {
        int m = m0 + ty * 4 + i;
        int b = m >> 9, r = m & 511;
#pragma unroll
        for (int j = 0; j < 4; j++) {
            int n = n0 + tx * 4 + j;
            float v = acc[i][j];
            if (mode == 0) {
                int h = n >> 4, kc = n & 15;
                Cout[(((b * Hh + h) * 512 + r) << 4) + kc] = v;
            } else if (mode == 1) {
                v += g_c1[b * HK + n] + tvec[m] * wq_last[n];
                int h = n >> 4, kc = n & 15;
                Cout[(((b * Hh + h) * 512 + r) << 4) + kc] = v;
            } else {
                Cout[m * 256 + n] = v + bias[n];
            }
        }
    }
}

// ---------------------------------------------------------------------------
// Attention: one block per (b, h, g-tile of 64). K_h/V_h staged in SMEM.
// ---------------------------------------------------------------------------
#define GT 64
// SMEM floats: sK 8192 | sV 8192 | sc 512 | sq 16 | sout 256 | sred 8 | sbc 2
#define ATTN_SMEM_FLOATS (8192 + 8192 + 512 + 16 + 256 + 8 + 2)
#define ATTN_SMEM_BYTES (ATTN_SMEM_FLOATS * 4)

__global__ __launch_bounds__(256)
void attn_kernel(const float* __restrict__ mask) {
    extern __shared__ float sm[];
    float* sK = sm;              // transposed [Kd][Pp]: sK[kc*512+p]
    float* sV = sm + 8192;       // natural [Pp][Kd]
    float* sc = sm + 16384;      // [512]
    float* sq = sc + 512;        // [16]
    float* sout = sq + 16;       // [256]
    float* sred = sout + 256;    // [8]
    float* sbc = sred + 8;       // [2]

    const int tid = threadIdx.x;
    const int b = blockIdx.z, h = blockIdx.y, g0 = blockIdx.x * GT;
    const float* Kb = g_Kt + (size_t)(b * Hh + h) * Pp * Kd;
    const float* Vb = g_Vt + (size_t)(b * Hh + h) * Pp * Kd;
    const float* Qb = g_Qt + (size_t)(b * Hh + h) * Gg * Kd;

    // Stage K (transposed) and V (natural) into SMEM
    for (int i = tid; i < (Pp * Kd) / 4; i += 256) {
        float4 kv = reinterpret_cast<const float4*>(Kb)[i];
        float4 vv = reinterpret_cast<const float4*>(Vb)[i];
        int p = i >> 2, c0 = (i & 3) * 4;
        sK[(c0 + 0) * Pp + p] = kv.x;
        sK[(c0 + 1) * Pp + p] = kv.y;
        sK[(c0 + 2) * Pp + p] = kv.z;
        sK[(c0 + 3) * Pp + p] = kv.w;
        reinterpret_cast<float4*>(sV)[i] = vv;
    }
    __syncthreads();

    for (int gi = 0; gi < GT; gi++) {
        int g = g0 + gi;
        if (tid < 16) sq[tid] = Qb[g * Kd + tid];
        __syncthreads();

        const float* mrow = mask + (size_t)(b * Gg + g) * Pp;
        float sv[2];
        float lmax = -3.0e38f;
#pragma unroll
        for (int u = 0; u < 2; u++) {
            int p = tid + u * 256;
            float s = 0.f;
#pragma unroll
            for (int kc = 0; kc < 16; kc++) s += sq[kc] * sK[kc * 512 + p];
            s = s * 0.25f + mrow[p];
            sv[u] = s;
            lmax = fmaxf(lmax, s);
        }
        // block max
#pragma unroll
        for (int o = 16; o > 0; o >>= 1)
            lmax = fmaxf(lmax, __shfl_xor_sync(0xffffffffu, lmax, o));
        if ((tid & 31) == 0) sred[tid >> 5] = lmax;
        __syncthreads();
        if (tid == 0) {
            float m = sred[0];
#pragma unroll
            for (int w = 1; w < 8; w++) m = fmaxf(m, sred[w]);
            sbc[0] = m;
        }
        __syncthreads();
        float smax = sbc[0];

        float lsum = 0.f;
#pragma unroll
        for (int u = 0; u < 2; u++) {
            float e = __expf(sv[u] - smax);
            sc[tid + u * 256] = e;
            lsum += e;
        }
#pragma unroll
        for (int o = 16; o > 0; o >>= 1)
            lsum += __shfl_xor_sync(0xffffffffu, lsum, o);
        if ((tid & 31) == 0) sred[tid >> 5] = lsum;
        __syncthreads();
        if (tid == 0) {
            float s = 0.f;
#pragma unroll
            for (int w = 0; w < 8; w++) s += sred[w];
            sbc[1] = 1.f / s;
        }
        __syncthreads();   // also publishes sc[] writes
        float inv = sbc[1];

        // out[kc] = inv * sum_p sc[p]*V[p][kc]
        int kc = tid & 15, pg = tid >> 4;
        float o = 0.f;
        for (int p = pg; p < Pp; p += 16) o += sc[p] * sV[p * 16 + kc];
        sout[tid] = o;
        __syncthreads();
        if (tid < 16) {
            float s = 0.f;
#pragma unroll
            for (int i = 0; i < 16; i++) s += sout[i * 16 + tid];
            g_attn[(size_t)(b * Gg + g) * HK + h * Kd + tid] = s * inv;
        }
        __syncthreads();
    }
}

// ---------------------------------------------------------------------------
// Pointer score: per batch, C[g,p] = mh[b,g,:]·enc[b,p,:] / 16, then
// 10*tanh + mask. Tiled 64x64 NT GEMM, fused epilogue.
// ---------------------------------------------------------------------------
__global__ __launch_bounds__(256)
void pointer_gemm(const float* __restrict__ enc, const float* __restrict__ mask) {
    __shared__ float As[16][68];   // transposed mh tile
    __shared__ float Bs[16][68];   // transposed enc tile
    const int tid = threadIdx.x;
    const int b = blockIdx.z;
    const int g0 = blockIdx.x * 64, p0 = blockIdx.y * 64;
    const float* A = g_mh + (size_t)b * Gg * HK;
    const float* Bm = enc + (size_t)b * Pp * Ee;
    const int tx = tid & 15, ty = tid >> 4;

    float acc[4][4];
#pragma unroll
    for (int i = 0; i < 4; i++)
#pragma unroll
        for (int j = 0; j < 4; j++) acc[i][j] = 0.f;

    const int ar = tid >> 2, ac4 = (tid & 3) * 4;

    for (int k0 = 0; k0 < 256; k0 += 16) {
        float4 av = *reinterpret_cast<const float4*>(A + (g0 + ar) * 256 + k0 + ac4);
        float4 bv = *reinterpret_cast<const float4*>(Bm + (p0 + ar) * 256 + k0 + ac4);
        As[ac4 + 0][ar] = av.x;
        As[ac4 + 1][ar] = av.y;
        As[ac4 + 2][ar] = av.z;
        As[ac4 + 3][ar] = av.w;
        Bs[ac4 + 0][ar] = bv.x;
        Bs[ac4 + 1][ar] = bv.y;
        Bs[ac4 + 2][ar] = bv.z;
        Bs[ac4 + 3][ar] = bv.w;
        __syncthreads();
#pragma unroll
        for (int kk = 0; kk < 16; kk++) {
            float4 a4 = *reinterpret_cast<const float4*>(&As[kk][ty * 4]);
            float4 b4 = *reinterpret_cast<const float4*>(&Bs[kk][tx * 4]);
            float aa[4] = {a4.x, a4.y, a4.z, a4.w};
            float bb[4] = {b4.x, b4.y, b4.z, b4.w};
#pragma unroll
            for (int i = 0; i < 4; i++)
#pragma unroll
                for (int j = 0; j < 4; j++) acc[i][j] += aa[i] * bb[j];
        }
        __syncthreads();
    }

#pragma unroll
    for (int i = 0; i < 4; i++) {
        int g = g0 + ty * 4 + i;
#pragma unroll
        for (int j = 0; j < 4; j++) {
            int p = p0 + tx * 4 + j;
            float v = acc[i][j] * 0.0625f;           // / sqrt(256)
            size_t idx = (size_t)(b * Gg + g) * Pp + p;
            g_s2[idx] = 10.f * tanhf(v) + mask[idx];
        }
    }
}

// ---------------------------------------------------------------------------
// Row softmax over P=512
// ---------------------------------------------------------------------------
__global__ __launch_bounds__(256)
void softmax_kernel(float* __restrict__ out) {
    __shared__ float sred[8];
    __shared__ float sbc[2];
    const int row = blockIdx.x;
    const int tid = threadIdx.x;
    const float* in = g_s2 + (size_t)row * Pp;

    float v0 = in[tid], v1 = in[tid + 256];
    float lmax = fmaxf(v0, v1);
#pragma unroll
    for (int o = 16; o > 0; o >>= 1)
        lmax = fmaxf(lmax, __shfl_xor_sync(0xffffffffu, lmax, o));
    if ((tid & 31) == 0) sred[tid >> 5] = lmax;
    __syncthreads();
    if (tid == 0) {
        float m = sred[0];
#pragma unroll
        for (int w = 1; w < 8; w++) m = fmaxf(m, sred[w]);
        sbc[0] = m;
    }
    __syncthreads();
    float smax = sbc[0];

    float e0 = __expf(v0 - smax), e1 = __expf(v1 - smax);
    float lsum = e0 + e1;
#pragma unroll
    for (int o = 16; o > 0; o >>= 1)
        lsum += __shfl_xor_sync(0xffffffffu, lsum, o);
    if ((tid & 31) == 0) sred[tid >> 5] = lsum;
    __syncthreads();
    if (tid == 0) {
        float s = 0.f;
#pragma unroll
        for (int w = 0; w < 8; w++) s += sred[w];
        sbc[1] = 1.f / s;
    }
    __syncthreads();
    float inv = sbc[1];
    out[(size_t)row * Pp + tid] = e0 * inv;
    out[(size_t)row * Pp + tid + 256] = e1 * inv;
}

// ---------------------------------------------------------------------------
extern "C" void kernel_launch(void* const* d_in, const int* in_sizes, int n_in,
                              void* d_out, int out_size) {
    const float* input1 = (const float*)d_in[0];   // [B,1,E]
    const float* input2 = (const float*)d_in[1];   // [B,G,E]
    const float* ctime  = (const float*)d_in[2];   // [B,G,1]
    const float* mask   = (const float*)d_in[3];   // [B,G,P]
    const float* enc    = (const float*)d_in[4];   // [B,P,E]
    const float* Wq     = (const float*)d_in[5];   // [2E+1, HK]
    const float* Wk     = (const float*)d_in[6];   // [E, HK]
    const float* Wv     = (const float*)d_in[7];   // [E, HK]
    const float* Wcw    = (const float*)d_in[8];   // [HK, E]
    const float* Wcb    = (const float*)d_in[9];   // [E]
    float* out = (float*)d_out;

    float *pKt, *pVt, *pQt, *pattn, *pmh;
    cudaGetSymbolAddress((void**)&pKt, g_Kt);
    cudaGetSymbolAddress((void**)&pVt, g_Vt);
    cudaGetSymbolAddress((void**)&pQt, g_Qt);
    cudaGetSymbolAddress((void**)&pattn, g_attn);
    cudaGetSymbolAddress((void**)&pmh, g_mh);

    // 1. q bias terms from input1
    qbias_kernel<<<Bb, 256>>>(input1, Wq);

    // 2-4. K, V, Q projections
    dim3 ggrid(128, 4);
    gemm_kernel<<<ggrid, 256>>>(enc,    Wk,             pKt, 0, nullptr, nullptr, nullptr);
    gemm_kernel<<<ggrid, 256>>>(enc,    Wv,             pVt, 0, nullptr, nullptr, nullptr);
    gemm_kernel<<<ggrid, 256>>>(input2, Wq + Ee * HK,   pQt, 1, ctime, Wq + 2 * Ee * HK, nullptr);

    // 5. attention
    cudaFuncSetAttribute(attn_kernel, cudaFuncAttributeMaxDynamicSharedMemorySize,
                         ATTN_SMEM_BYTES);
    attn_kernel<<<dim3(Gg / GT, Hh, Bb), 256, ATTN_SMEM_BYTES>>>(mask);

    // 6. output projection
    gemm_kernel<<<ggrid, 256>>>(pattn, Wcw, pmh, 2, nullptr, nullptr, Wcb);

    // 7. pointer scores with tanh clip + mask
    pointer_gemm<<<dim3(8, 8, Bb), 256>>>(enc, mask);

    // 8. final softmax
    softmax_kernel<<<Bb * Gg, 256>>>(out);
}

// round 2
// speedup vs baseline: 1.2694x; 1.2694x over previous
#include <cuda_runtime.h>
#include <math.h>

#define Bb 16
#define Gg 512
#define Pp 512
#define Ee 256
#define Hh 16
#define Kd 16
#define HK 256

// Scratch (device globals: allocation-free rule)
__device__ float g_c1[Bb * HK];
__device__ float g_Kt[Bb * Hh * Pp * Kd];   // [B,H,P,Kd]
__device__ float g_Vt[Bb * Hh * Pp * Kd];
__device__ float g_Qt[Bb * Hh * Gg * Kd];
__device__ float g_attn[Bb * Gg * HK];
__device__ float g_mh[Bb * Gg * HK];
__device__ float g_s2[Bb * Gg * Pp];

// ---------------------------------------------------------------------------
__global__ void qbias_kernel(const float* __restrict__ input1,
                             const float* __restrict__ Wq) {
    int b = blockIdx.x;
    int n = threadIdx.x;
    const float* x = input1 + b * Ee;
    float acc = 0.f;
#pragma unroll 4
    for (int e = 0; e < Ee; e++) acc += x[e] * Wq[e * HK + n];
    g_c1[b * HK + n] = acc;
}

// ---------------------------------------------------------------------------
// 128x128 tile GEMM core pieces (256 threads, 8x8 micro-tile, BK=8)
// A is [M,256] row-major, W is [256,N] row-major.
// ---------------------------------------------------------------------------
#define GEMM_PROLOG()                                                     \
    __shared__ float As[8][132];                                          \
    __shared__ float Bs[8][132];                                          \
    const int tid = threadIdx.x;                                          \
    const int warp = tid >> 5, lane = tid & 31;                           \
    const int tm = ((warp >> 2) << 3) + (lane >> 2);                      \
    const int tn = ((warp & 3) << 2) + (lane & 3);                        \
    const int ar = tid >> 1, ac = (tid & 1) * 4;                          \
    const int br = tid >> 5, bc = (tid & 31) * 4;                         \
    float acc[8][8];                                                      \
    _Pragma("unroll") for (int i = 0; i < 8; i++)                         \
    _Pragma("unroll") for (int j = 0; j < 8; j++) acc[i][j] = 0.f;

#define GEMM_INNER()                                                      \
    _Pragma("unroll")                                                     \
    for (int kk = 0; kk < 8; kk++) {                                      \
        float4 a0 = *(const float4*)&As[kk][tm * 8];                      \
        float4 a1 = *(const float4*)&As[kk][tm * 8 + 4];                  \
        float4 b0 = *(const float4*)&Bs[kk][tn * 8];                      \
        float4 b1 = *(const float4*)&Bs[kk][tn * 8 + 4];                  \
        float aa[8] = {a0.x, a0.y, a0.z, a0.w, a1.x, a1.y, a1.z, a1.w};   \
        float bb[8] = {b0.x, b0.y, b0.z, b0.w, b1.x, b1.y, b1.z, b1.w};   \
        _Pragma("unroll") for (int i = 0; i < 8; i++)                     \
        _Pragma("unroll") for (int j = 0; j < 8; j++)                     \
            acc[i][j] += aa[i] * bb[j];                                   \
    }

// NN mainloop: W accessed [k][n]
#define GEMM_LOOP_NN(Aptr, Wptr, m0, n0)                                  \
    for (int k0 = 0; k0 < 256; k0 += 8) {                                 \
        float4 av = *(const float4*)((Aptr) + (size_t)((m0) + ar) * 256 + k0 + ac); \
        float4 bv = *(const float4*)((Wptr) + (size_t)(k0 + br) * 256 + (n0) + bc); \
        As[ac + 0][ar] = av.x; As[ac + 1][ar] = av.y;                     \
        As[ac + 2][ar] = av.z; As[ac + 3][ar] = av.w;                     \
        *(float4*)&Bs[br][bc] = bv;                                       \
        __syncthreads();                                                  \
        GEMM_INNER();                                                     \
        __syncthreads();                                                  \
    }

// NT mainloop: second operand also [n][k] row-major (K contiguous)
#define GEMM_LOOP_NT(Aptr, Bptr, m0, n0)                                  \
    for (int k0 = 0; k0 < 256; k0 += 8) {                                 \
        float4 av = *(const float4*)((Aptr) + (size_t)((m0) + ar) * 256 + k0 + ac); \
        float4 bv = *(const float4*)((Bptr) + (size_t)((n0) + ar) * 256 + k0 + ac); \
        As[ac + 0][ar] = av.x; As[ac + 1][ar] = av.y;                     \
        As[ac + 2][ar] = av.z; As[ac + 3][ar] = av.w;                     \
        Bs[ac + 0][ar] = bv.x; Bs[ac + 1][ar] = bv.y;                     \
        Bs[ac + 2][ar] = bv.z; Bs[ac + 3][ar] = bv.w;                     \
        __syncthreads();                                                  \
        GEMM_INNER();                                                     \
        __syncthreads();                                                  \
    }

// ---------------------------------------------------------------------------
// Fused projection kernel: z=0 -> K, z=1 -> V, z=2 -> Q (with c1 + t*wq_last)
// Output in heads layout [B,H,512,16].
// ---------------------------------------------------------------------------
__global__ __launch_bounds__(256, 2)
void proj_kernel(const float* __restrict__ enc, const float* __restrict__ inp2,
                 const float* __restrict__ Wk, const float* __restrict__ Wv,
                 const float* __restrict__ Wqm, const float* __restrict__ tvec,
                 const float* __restrict__ wql) {
    const int z = blockIdx.z;
    const float* A = (z == 2) ? inp2 : enc;
    const float* W = (z == 0) ? Wk : (z == 1) ? Wv : Wqm;
    float* C = (z == 0) ? g_Kt : (z == 1) ? g_Vt : g_Qt;
    const int m0 = blockIdx.x * 128, n0 = blockIdx.y * 128;

    GEMM_PROLOG();
    GEMM_LOOP_NN(A, W, m0, n0);

#pragma unroll
    for (int i = 0; i < 8; i++) {
        int m = m0 + tm * 8 + i;
        int bb = m >> 9, r = m & 511;
        int nb = n0 + tn * 8;
        float v[8];
        float t = (z == 2) ? tvec[m] : 0.f;
#pragma unroll
        for (int j = 0; j < 8; j++) {
            v[j] = acc[i][j];
            if (z == 2) {
                int n = nb + j;
                v[j] += g_c1[bb * HK + n] + t * wql[n];
            }
        }
        int h = nb >> 4, kcb = nb & 15;
        float* dst = C + (((size_t)(bb * Hh + h) * 512 + r) << 4) + kcb;
        *(float4*)dst = make_float4(v[0], v[1], v[2], v[3]);
        *(float4*)(dst + 4) = make_float4(v[4], v[5], v[6], v[7]);
    }
}

// ---------------------------------------------------------------------------
// Output projection: g_mh = g_attn @ Wcw + Wcb   (flat [8192,256])
// ---------------------------------------------------------------------------
__global__ __launch_bounds__(256, 2)
void wc_kernel(const float* __restrict__ Wcw, const float* __restrict__ bias) {
    const int m0 = blockIdx.x * 128, n0 = blockIdx.y * 128;
    GEMM_PROLOG();
    GEMM_LOOP_NN(g_attn, Wcw, m0, n0);

#pragma unroll
    for (int i = 0; i < 8; i++) {
        int m = m0 + tm * 8 + i;
        int nb = n0 + tn * 8;
        float* dst = g_mh + (size_t)m * 256 + nb;
        *(float4*)dst = make_float4(acc[i][0] + bias[nb + 0], acc[i][1] + bias[nb + 1],
                                    acc[i][2] + bias[nb + 2], acc[i][3] + bias[nb + 3]);
        *(float4*)(dst + 4) = make_float4(acc[i][4] + bias[nb + 4], acc[i][5] + bias[nb + 5],
                                          acc[i][6] + bias[nb + 6], acc[i][7] + bias[nb + 7]);
    }
}

// ---------------------------------------------------------------------------
// Pointer score GEMM (NT, per batch): s2 = 10*tanh((mh . enc)/16) + mask
// ---------------------------------------------------------------------------
__global__ __launch_bounds__(256, 2)
void pointer_gemm(const float* __restrict__ enc, const float* __restrict__ mask) {
    const int b = blockIdx.z;
    const int g0 = blockIdx.x * 128, p0 = blockIdx.y * 128;
    const float* A = g_mh + (size_t)b * Gg * HK;
    const float* Bm = enc + (size_t)b * Pp * Ee;

    GEMM_PROLOG();
    GEMM_LOOP_NT(A, Bm, g0, p0);

#pragma unroll
    for (int i = 0; i < 8; i++) {
        int g = g0 + tm * 8 + i;
        size_t base = (size_t)(b * Gg + g) * Pp + p0 + tn * 8;
        float v[8];
#pragma unroll
        for (int j = 0; j < 8; j++)
            v[j] = 10.f * tanhf(acc[i][j] * 0.0625f) + mask[base + j];
        *(float4*)&g_s2[base] = make_float4(v[0], v[1], v[2], v[3]);
        *(float4*)&g_s2[base + 4] = make_float4(v[4], v[5], v[6], v[7]);
    }
}

// ---------------------------------------------------------------------------
// Attention: block = (g-half, h, b). 256 queries per block, 8 per pass.
// K columns in registers (2 per thread), V in SMEM (pad-20), warp-per-row softmax.
// ---------------------------------------------------------------------------
#define ATTN_SMEM_FLOATS (10240 + 4096 + 128 + 1024 + 8)
#define ATTN_SMEM_BYTES (ATTN_SMEM_FLOATS * 4)

__global__ __launch_bounds__(256, 3)
void attn_kernel(const float* __restrict__ mask) {
    extern __shared__ float sm[];
    float* sV = sm;             // [512][20]
    float* sS = sm + 10240;     // [8][512] raw scores -> exp weights
    float* sq = sS + 4096;      // [8][16]
    float* sO = sq + 128;       // [8][16][8] partials
    float* sinv = sO + 1024;    // [8]

    const int tid = threadIdx.x;
    const int gbase = blockIdx.x * 256;
    const int h = blockIdx.y, b = blockIdx.z;
    const float* Kb = g_Kt + (size_t)(b * Hh + h) * Pp * Kd;
    const float* Vb = g_Vt + (size_t)(b * Hh + h) * Pp * Kd;
    const float* Qb = g_Qt + (size_t)(b * Hh + h) * Gg * Kd;

    // Stage V into SMEM (padded stride 20, keeps float4 alignment)
    for (int i = tid; i < 2048; i += 256) {
        float4 vv = reinterpret_cast<const float4*>(Vb)[i];
        int p = i >> 2, c0 = (i & 3) * 4;
        *(float4*)&sV[p * 20 + c0] = vv;
    }

    // K columns for this thread's two key indices -> registers (coalesced)
    const int p0 = tid, p1 = tid + 256;
    float k0r[16], k1r[16];
    {
        float4 x0 = *(const float4*)(Kb + p0 * 16);
        float4 x1 = *(const float4*)(Kb + p0 * 16 + 4);
        float4 x2 = *(const float4*)(Kb + p0 * 16 + 8);
        float4 x3 = *(const float4*)(Kb + p0 * 16 + 12);
        k0r[0]=x0.x;k0r[1]=x0.y;k0r[2]=x0.z;k0r[3]=x0.w;
        k0r[4]=x1.x;k0r[5]=x1.y;k0r[6]=x1.z;k0r[7]=x1.w;
        k0r[8]=x2.x;k0r[9]=x2.y;k0r[10]=x2.z;k0r[11]=x2.w;
        k0r[12]=x3.x;k0r[13]=x3.y;k0r[14]=x3.z;k0r[15]=x3.w;
        float4 y0 = *(const float4*)(Kb + p1 * 16);
        float4 y1 = *(const float4*)(Kb + p1 * 16 + 4);
        float4 y2 = *(const float4*)(Kb + p1 * 16 + 8);
        float4 y3 = *(const float4*)(Kb + p1 * 16 + 12);
        k1r[0]=y0.x;k1r[1]=y0.y;k1r[2]=y0.z;k1r[3]=y0.w;
        k1r[4]=y1.x;k1r[5]=y1.y;k1r[6]=y1.z;k1r[7]=y1.w;
        k1r[8]=y2.x;k1r[9]=y2.y;k1r[10]=y2.z;k1r[11]=y2.w;
        k1r[12]=y3.x;k1r[13]=y3.y;k1r[14]=y3.z;k1r[15]=y3.w;
    }
    __syncthreads();

    const int warp = tid >> 5, lane = tid & 31;

    for (int pass = 0; pass < 32; pass++) {
        const int g0q = gbase + pass * 8;

        // load 8 query vectors
        if (tid < 128) sq[tid] = Qb[(g0q + (tid >> 4)) * 16 + (tid & 15)];
        __syncthreads();

        // scores: each thread handles keys p0, p1 for all 8 queries
#pragma unroll
        for (int q = 0; q < 8; q++) {
            float4 qa = *(const float4*)&sq[q * 16];
            float4 qb2 = *(const float4*)&sq[q * 16 + 4];
            float4 qc = *(const float4*)&sq[q * 16 + 8];
            float4 qd = *(const float4*)&sq[q * 16 + 12];
            float qv[16] = {qa.x,qa.y,qa.z,qa.w, qb2.x,qb2.y,qb2.z,qb2.w,
                            qc.x,qc.y,qc.z,qc.w, qd.x,qd.y,qd.z,qd.w};
            float s0 = 0.f, s1 = 0.f;
#pragma unroll
            for (int kc = 0; kc < 16; kc++) {
                s0 += qv[kc] * k0r[kc];
                s1 += qv[kc] * k1r[kc];
            }
            const float* mrow = mask + (size_t)(b * Gg + g0q + q) * Pp;
            sS[q * 512 + p0] = s0 * 0.25f + mrow[p0];
            sS[q * 512 + p1] = s1 * 0.25f + mrow[p1];
        }
        __syncthreads();

        // softmax: warp w owns row w (512 elements, 16/lane)
        {
            float* row = sS + warp * 512;
            float v[16];
#pragma unroll
            for (int j = 0; j < 16; j++) v[j] = row[lane + j * 32];
            float mx = v[0];
#pragma unroll
            for (int j = 1; j < 16; j++) mx = fmaxf(mx, v[j]);
#pragma unroll
            for (int o = 16; o > 0; o >>= 1)
                mx = fmaxf(mx, __shfl_xor_sync(0xffffffffu, mx, o));
            float sum = 0.f;
#pragma unroll
            for (int j = 0; j < 16; j++) {
                float e = __expf(v[j] - mx);
                row[lane + j * 32] = e;
                sum += e;
            }
#pragma unroll
            for (int o = 16; o > 0; o >>= 1)
                sum += __shfl_xor_sync(0xffffffffu, sum, o);
            if (lane == 0) sinv[warp] = 1.f / sum;
        }
        __syncthreads();

        // O phase: warp = query; lane -> (kc4, grp); p = grp + 8*i
        {
            const int kc4 = (lane & 3) * 4;
            const int grp = lane >> 2;
            const float* srow = sS + warp * 512;
            float4 o = make_float4(0.f, 0.f, 0.f, 0.f);
#pragma unroll 8
            for (int i2 = 0; i2 < 64; i2++) {
                int p = grp + (i2 << 3);
                float w = srow[p];
                float4 v4 = *(const float4*)&sV[p * 20 + kc4];
                o.x += w * v4.x; o.y += w * v4.y;
                o.z += w * v4.z; o.w += w * v4.w;
            }
            int base = (warp * 16 + kc4) * 8 + grp;
            sO[base] = o.x;
            sO[base + 8] = o.y;
            sO[base + 16] = o.z;
            sO[base + 24] = o.w;
        }
        __syncthreads();

        // reduce partials + write out
        if (tid < 128) {
            int q = tid >> 4, kc = tid & 15;
            float4 x = *(const float4*)&sO[tid * 8];
            float4 y = *(const float4*)&sO[tid * 8 + 4];
            float s = x.x + x.y + x.z + x.w + y.x + y.y + y.z + y.w;
            g_attn[(size_t)(b * Gg + g0q + q) * HK + h * Kd + kc] = s * sinv[q];
        }
        // no barrier needed here: next pass's first barrier orders everything
    }
}

// ---------------------------------------------------------------------------
// Row softmax over P=512
// ---------------------------------------------------------------------------
__global__ __launch_bounds__(256)
void softmax_kernel(float* __restrict__ out) {
    __shared__ float sred[8];
    __shared__ float sbc[2];
    const int row = blockIdx.x;
    const int tid = threadIdx.x;
    const float* in = g_s2 + (size_t)row * Pp;

    float v0 = in[tid], v1 = in[tid + 256];
    float lmax = fmaxf(v0, v1);
#pragma unroll
    for (int o = 16; o > 0; o >>= 1)
        lmax = fmaxf(lmax, __shfl_xor_sync(0xffffffffu, lmax, o));
    if ((tid & 31) == 0) sred[tid >> 5] = lmax;
    __syncthreads();
    if (tid == 0) {
        float m = sred[0];
#pragma unroll
        for (int w = 1; w < 8; w++) m = fmaxf(m, sred[w]);
        sbc[0] = m;
    }
    __syncthreads();
    float smax = sbc[0];

    float e0 = __expf(v0 - smax), e1 = __expf(v1 - smax);
    float lsum = e0 + e1;
#pragma unroll
    for (int o = 16; o > 0; o >>= 1)
        lsum += __shfl_xor_sync(0xffffffffu, lsum, o);
    if ((tid & 31) == 0) sred[tid >> 5] = lsum;
    __syncthreads();
    if (tid == 0) {
        float s = 0.f;
#pragma unroll
        for (int w = 0; w < 8; w++) s += sred[w];
        sbc[1] = 1.f / s;
    }
    __syncthreads();
    float inv = sbc[1];
    out[(size_t)row * Pp + tid] = e0 * inv;
    out[(size_t)row * Pp + tid + 256] = e1 * inv;
}

// ---------------------------------------------------------------------------
extern "C" void kernel_launch(void* const* d_in, const int* in_sizes, int n_in,
                              void* d_out, int out_size) {
    const float* input1 = (const float*)d_in[0];
    const float* input2 = (const float*)d_in[1];
    const float* ctime  = (const float*)d_in[2];
    const float* mask   = (const float*)d_in[3];
    const float* enc    = (const float*)d_in[4];
    const float* Wq     = (const float*)d_in[5];
    const float* Wk     = (const float*)d_in[6];
    const float* Wv     = (const float*)d_in[7];
    const float* Wcw    = (const float*)d_in[8];
    const float* Wcb    = (const float*)d_in[9];
    float* out = (float*)d_out;

    qbias_kernel<<<Bb, 256>>>(input1, Wq);

    proj_kernel<<<dim3(64, 2, 3), 256>>>(enc, input2, Wk, Wv,
                                         Wq + Ee * HK, ctime, Wq + 2 * Ee * HK);

    cudaFuncSetAttribute(attn_kernel, cudaFuncAttributeMaxDynamicSharedMemorySize,
                         ATTN_SMEM_BYTES);
    attn_kernel<<<dim3(2, Hh, Bb), 256, ATTN_SMEM_BYTES>>>(mask);

    wc_kernel<<<dim3(64, 2), 256>>>(Wcw, Wcb);

    pointer_gemm<<<dim3(4, 4, Bb), 256>>>(enc, mask);

    softmax_kernel<<<Bb * Gg, 256>>>(out);
}

// round 3
// speedup vs baseline: 1.7215x; 1.3562x over previous
#include <cuda_runtime.h>
#include <math.h>

#define Bb 16
#define Gg 512
#define Pp 512
#define Ee 256
#define Hh 16
#define Kd 16
#define HK 256

typedef unsigned long long ull;

// Scratch (device globals: allocation-free rule)
__device__ float g_c1[Bb * HK];
__device__ float g_Kt[Bb * Hh * Pp * Kd];   // [B,H,P,Kd]
__device__ float g_Vt[Bb * Hh * Pp * Kd];
__device__ float g_Qt[Bb * Hh * Gg * Kd];
__device__ float g_attn[Bb * Gg * HK];
__device__ float g_mh[Bb * Gg * HK];
__device__ float g_s2[Bb * Gg * Pp];

// ---- packed f32x2 helpers (Blackwell double-rate fp32) ---------------------
__device__ __forceinline__ ull dup2(float a) {
    ull r; asm("mov.b64 %0, {%1, %1};" : "=l"(r) : "f"(a)); return r;
}
__device__ __forceinline__ void fma2(ull& d, ull a, ull b) {
    asm("fma.rn.f32x2 %0, %1, %2, %3;" : "=l"(d) : "l"(a), "l"(b), "l"(d));
}
__device__ __forceinline__ float2 unpack2(ull v) {
    float2 f; asm("mov.b64 {%0, %1}, %2;" : "=f"(f.x), "=f"(f.y) : "l"(v)); return f;
}

// ---------------------------------------------------------------------------
__global__ void qbias_kernel(const float* __restrict__ input1,
                             const float* __restrict__ Wq) {
    int b = blockIdx.x;
    int n = threadIdx.x;
    const float* x = input1 + b * Ee;
    float acc = 0.f;
#pragma unroll 4
    for (int e = 0; e < Ee; e++) acc += x[e] * Wq[e * HK + n];
    g_c1[b * HK + n] = acc;
}

// ---------------------------------------------------------------------------
// 128x128 tile GEMM (256 threads, 8x8 micro-tile via 8x4 packed f32x2, BK=8)
// ---------------------------------------------------------------------------
#define GEMM_PROLOG()                                                     \
    __shared__ float As[8][132];                                          \
    __shared__ float Bs[8][132];                                          \
    const int tid = threadIdx.x;                                          \
    const int warp = tid >> 5, lane = tid & 31;                           \
    const int tm = ((warp >> 2) << 3) + (lane >> 2);                      \
    const int tn = ((warp & 3) << 2) + (lane & 3);                        \
    const int ar = tid >> 1, ac = (tid & 1) * 4;                          \
    const int br = tid >> 5, bc = (tid & 31) * 4;                         \
    ull acc2[8][4];                                                       \
    _Pragma("unroll") for (int i = 0; i < 8; i++)                         \
    _Pragma("unroll") for (int j = 0; j < 4; j++) acc2[i][j] = 0ull;

#define GEMM_INNER2()                                                     \
    _Pragma("unroll")                                                     \
    for (int kk = 0; kk < 8; kk++) {                                      \
        float4 a0 = *(const float4*)&As[kk][tm * 8];                      \
        float4 a1 = *(const float4*)&As[kk][tm * 8 + 4];                  \
        const ull* bp = (const ull*)&Bs[kk][tn * 8];                      \
        ull b0 = bp[0], b1 = bp[1], b2 = bp[2], b3 = bp[3];               \
        float aa[8] = {a0.x, a0.y, a0.z, a0.w, a1.x, a1.y, a1.z, a1.w};   \
        _Pragma("unroll") for (int i = 0; i < 8; i++) {                   \
            ull ad = dup2(aa[i]);                                         \
            fma2(acc2[i][0], ad, b0);                                     \
            fma2(acc2[i][1], ad, b1);                                     \
            fma2(acc2[i][2], ad, b2);                                     \
            fma2(acc2[i][3], ad, b3);                                     \
        }                                                                 \
    }

// NN mainloop with global prefetch double-buffering
#define GEMM_LOOP_NN(Aptr, Wptr, m0, n0)                                  \
    {                                                                     \
        const float* Ag = (Aptr) + (size_t)((m0) + ar) * 256 + ac;        \
        const float* Bg = (Wptr) + (size_t)br * 256 + (n0) + bc;          \
        float4 av = *(const float4*)Ag;                                   \
        float4 bv = *(const float4*)Bg;                                   \
        for (int k0 = 0; k0 < 256; k0 += 8) {                             \
            As[ac + 0][ar] = av.x; As[ac + 1][ar] = av.y;                 \
            As[ac + 2][ar] = av.z; As[ac + 3][ar] = av.w;                 \
            *(float4*)&Bs[br][bc] = bv;                                   \
            __syncthreads();                                              \
            if (k0 < 248) {                                               \
                av = *(const float4*)(Ag + k0 + 8);                       \
                bv = *(const float4*)(Bg + (size_t)(k0 + 8) * 256);       \
            }                                                             \
            GEMM_INNER2();                                                \
            __syncthreads();                                              \
        }                                                                 \
    }

// NT mainloop (both operands [row][k] row-major)
#define GEMM_LOOP_NT(Aptr, Bptr, m0, n0)                                  \
    {                                                                     \
        const float* Ag = (Aptr) + (size_t)((m0) + ar) * 256 + ac;        \
        const float* Bg2 = (Bptr) + (size_t)((n0) + ar) * 256 + ac;       \
        float4 av = *(const float4*)Ag;                                   \
        float4 bv = *(const float4*)Bg2;                                  \
        for (int k0 = 0; k0 < 256; k0 += 8) {                             \
            As[ac + 0][ar] = av.x; As[ac + 1][ar] = av.y;                 \
            As[ac + 2][ar] = av.z; As[ac + 3][ar] = av.w;                 \
            Bs[ac + 0][ar] = bv.x; Bs[ac + 1][ar] = bv.y;                 \
            Bs[ac + 2][ar] = bv.z; Bs[ac + 3][ar] = bv.w;                 \
            __syncthreads();                                              \
            if (k0 < 248) {                                               \
                av = *(const float4*)(Ag + k0 + 8);                       \
                bv = *(const float4*)(Bg2 + k0 + 8);                      \
            }                                                             \
            GEMM_INNER2();                                                \
            __syncthreads();                                              \
        }                                                                 \
    }

// ---------------------------------------------------------------------------
// Fused projections: z=0 K, z=1 V, z=2 Q (+c1 + t*wq_last). Heads layout out.
// ---------------------------------------------------------------------------
__global__ __launch_bounds__(256, 2)
void proj_kernel(const float* __restrict__ enc, const float* __restrict__ inp2,
                 const float* __restrict__ Wk, const float* __restrict__ Wv,
                 const float* __restrict__ Wqm, const float* __restrict__ tvec,
                 const float* __restrict__ wql) {
    const int z = blockIdx.z;
    const float* A = (z == 2) ? inp2 : enc;
    const float* W = (z == 0) ? Wk : (z == 1) ? Wv : Wqm;
    float* C = (z == 0) ? g_Kt : (z == 1) ? g_Vt : g_Qt;
    const int m0 = blockIdx.x * 128, n0 = blockIdx.y * 128;

    GEMM_PROLOG();
    GEMM_LOOP_NN(A, W, m0, n0);

#pragma unroll
    for (int i = 0; i < 8; i++) {
        int m = m0 + tm * 8 + i;
        int bb = m >> 9, r = m & 511;
        int nb = n0 + tn * 8;
        float v[8];
#pragma unroll
        for (int j = 0; j < 4; j++) {
            float2 f = unpack2(acc2[i][j]);
            v[2 * j] = f.x; v[2 * j + 1] = f.y;
        }
        if (z == 2) {
            float t = tvec[m];
#pragma unroll
            for (int j = 0; j < 8; j++) {
                int n = nb + j;
                v[j] += g_c1[bb * HK + n] + t * wql[n];
            }
        }
        int h = nb >> 4, kcb = nb & 15;
        float* dst = C + (((size_t)(bb * Hh + h) * 512 + r) << 4) + kcb;
        *(float4*)dst = make_float4(v[0], v[1], v[2], v[3]);
        *(float4*)(dst + 4) = make_float4(v[4], v[5], v[6], v[7]);
    }
}

// ---------------------------------------------------------------------------
__global__ __launch_bounds__(256, 2)
void wc_kernel(const float* __restrict__ Wcw, const float* __restrict__ bias) {
    const int m0 = blockIdx.x * 128, n0 = blockIdx.y * 128;
    GEMM_PROLOG();
    GEMM_LOOP_NN(g_attn, Wcw, m0, n0);

#pragma unroll
    for (int i = 0; i < 8; i++) {
        int m = m0 + tm * 8 + i;
        int nb = n0 + tn * 8;
        float v[8];
#pragma unroll
        for (int j = 0; j < 4; j++) {
            float2 f = unpack2(acc2[i][j]);
            v[2 * j] = f.x + bias[nb + 2 * j];
            v[2 * j + 1] = f.y + bias[nb + 2 * j + 1];
        }
        float* dst = g_mh + (size_t)m * 256 + nb;
        *(float4*)dst = make_float4(v[0], v[1], v[2], v[3]);
        *(float4*)(dst + 4) = make_float4(v[4], v[5], v[6], v[7]);
    }
}

// ---------------------------------------------------------------------------
__device__ __forceinline__ float fast_tanh10(float x) {
    // 10 * tanh(x), |err| ~1e-6 rel
    x = fminf(fmaxf(x, -15.f), 15.f);
    float e = __expf(2.f * x);
    return 10.f * (1.f - __fdividef(2.f, e + 1.f));
}

__global__ __launch_bounds__(256, 2)
void pointer_gemm(const float* __restrict__ enc, const float* __restrict__ mask) {
    const int b = blockIdx.z;
    const int g0 = blockIdx.x * 128, p0 = blockIdx.y * 128;
    const float* A = g_mh + (size_t)b * Gg * HK;
    const float* Bm = enc + (size_t)b * Pp * Ee;

    GEMM_PROLOG();
    GEMM_LOOP_NT(A, Bm, g0, p0);

#pragma unroll
    for (int i = 0; i < 8; i++) {
        int g = g0 + tm * 8 + i;
        size_t base = (size_t)(b * Gg + g) * Pp + p0 + tn * 8;
        float v[8];
#pragma unroll
        for (int j = 0; j < 4; j++) {
            float2 f = unpack2(acc2[i][j]);
            v[2 * j] = fast_tanh10(f.x * 0.0625f) + mask[base + 2 * j];
            v[2 * j + 1] = fast_tanh10(f.y * 0.0625f) + mask[base + 2 * j + 1];
        }
        *(float4*)&g_s2[base] = make_float4(v[0], v[1], v[2], v[3]);
        *(float4*)&g_s2[base + 4] = make_float4(v[4], v[5], v[6], v[7]);
    }
}

// ---------------------------------------------------------------------------
// Attention. Block = (g-half, h, b): 256 queries, 8 per pass.
// K cols in regs (packed pairs), V in SMEM stride-17, O-phase reads V once/pass.
// ---------------------------------------------------------------------------
#define SV_STR 17
#define ATTN_SMEM_FLOATS (512 * SV_STR + 4096 + 128 + 16 * 132 + 8)
#define ATTN_SMEM_BYTES (ATTN_SMEM_FLOATS * 4)

__global__ __launch_bounds__(256, 3)
void attn_kernel(const float* __restrict__ mask) {
    extern __shared__ float sm[];
    float* sV = sm;                    // [512][17]
    float* sS = sm + 512 * SV_STR;     // [8][512]
    float* sq = sS + 4096;             // [8][16]
    float* sO = sq + 128;              // [16][132] partials (pg-major)
    float* sinv = sO + 16 * 132;       // [8]

    const int tid = threadIdx.x;
    const int gbase = blockIdx.x * 256;
    const int h = blockIdx.y, b = blockIdx.z;
    const float* Kb = g_Kt + (size_t)(b * Hh + h) * Pp * Kd;
    const float* Vb = g_Vt + (size_t)(b * Hh + h) * Pp * Kd;
    const float* Qb = g_Qt + (size_t)(b * Hh + h) * Gg * Kd;

    // Stage V (stride 17)
    for (int i = tid; i < 2048; i += 256) {
        float4 vv = reinterpret_cast<const float4*>(Vb)[i];
        int p = i >> 2, c0 = (i & 3) * 4;
        float* d = &sV[p * SV_STR + c0];
        d[0] = vv.x; d[1] = vv.y; d[2] = vv.z; d[3] = vv.w;
    }

    // This thread's two K columns -> packed register pairs
    const int p0 = tid, p1 = tid + 256;
    ull k0p[8], k1p[8];
    {
        const ulonglong2* K0 = (const ulonglong2*)(Kb + p0 * 16);
        const ulonglong2* K1 = (const ulonglong2*)(Kb + p1 * 16);
#pragma unroll
        for (int j = 0; j < 4; j++) {
            ulonglong2 u = K0[j]; k0p[2 * j] = u.x; k0p[2 * j + 1] = u.y;
            ulonglong2 w = K1[j]; k1p[2 * j] = w.x; k1p[2 * j + 1] = w.y;
        }
    }
    __syncthreads();

    const int warp = tid >> 5, lane = tid & 31;
    const int kc = tid & 15, pg = tid >> 4;

    for (int pass = 0; pass < 32; pass++) {
        const int g0q = gbase + pass * 8;

        if (tid < 128) sq[tid] = Qb[(g0q + (tid >> 4)) * 16 + (tid & 15)];

        // prefetch mask values (coalesced LDG, overlaps barrier)
        float mk0[8], mk1[8];
        const float* mbase = mask + (size_t)(b * Gg + g0q) * Pp;
#pragma unroll
        for (int q = 0; q < 8; q++) {
            mk0[q] = mbase[q * Pp + p0];
            mk1[q] = mbase[q * Pp + p1];
        }
        __syncthreads();   // A

        // scores (packed f32x2 dot products)
#pragma unroll
        for (int q = 0; q < 8; q++) {
            const ull* q2 = (const ull*)&sq[q * 16];
            ull s0p = 0ull, s1p = 0ull;
#pragma unroll
            for (int j = 0; j < 8; j++) {
                ull qj = q2[j];
                fma2(s0p, qj, k0p[j]);
                fma2(s1p, qj, k1p[j]);
            }
            float2 f0 = unpack2(s0p), f1 = unpack2(s1p);
            sS[q * 512 + p0] = (f0.x + f0.y) * 0.25f + mk0[q];
            sS[q * 512 + p1] = (f1.x + f1.y) * 0.25f + mk1[q];
        }
        __syncthreads();   // B

        // softmax: warp w owns row w
        {
            float* row = sS + warp * 512;
            float v[16];
#pragma unroll
            for (int j = 0; j < 16; j++) v[j] = row[lane + j * 32];
            float mx = v[0];
#pragma unroll
            for (int j = 1; j < 16; j++) mx = fmaxf(mx, v[j]);
#pragma unroll
            for (int o = 16; o > 0; o >>= 1)
                mx = fmaxf(mx, __shfl_xor_sync(0xffffffffu, mx, o));
            float sum = 0.f;
#pragma unroll
            for (int j = 0; j < 16; j++) {
                float e = __expf(v[j] - mx);
                row[lane + j * 32] = e;
                sum += e;
            }
#pragma unroll
            for (int o = 16; o > 0; o >>= 1)
                sum += __shfl_xor_sync(0xffffffffu, sum, o);
            if (lane == 0) sinv[warp] = 1.f / sum;
        }
        __syncthreads();   // C

        // O phase: thread (kc, pg) walks 32 p's; V read ONCE per pass
        {
            float o[8];
#pragma unroll
            for (int q = 0; q < 8; q++) o[q] = 0.f;
#pragma unroll 4
            for (int i2 = 0; i2 < 32; i2++) {
                int p = pg + (i2 << 4);
                float v = sV[p * SV_STR + kc];
#pragma unroll
                for (int q = 0; q < 8; q++) o[q] += sS[q * 512 + p] * v;
            }
            float* dst = &sO[pg * 132 + kc];
#pragma unroll
            for (int q = 0; q < 8; q++) dst[q * 16] = o[q];
        }
        __syncthreads();   // D

        // reduce over 16 pg groups + write out
        if (tid < 128) {
            int q = tid >> 4, k2 = tid & 15;
            float s = 0.f;
#pragma unroll
            for (int g2 = 0; g2 < 16; g2++) s += sO[g2 * 132 + q * 16 + k2];
            g_attn[(size_t)(b * Gg + g0q + q) * HK + h * Kd + k2] = s * sinv[q];
        }
    }
}

// ---------------------------------------------------------------------------
__global__ __launch_bounds__(256)
void softmax_kernel(float* __restrict__ out) {
    __shared__ float sred[8];
    __shared__ float sbc[2];
    const int row = blockIdx.x;
    const int tid = threadIdx.x;
    const float* in = g_s2 + (size_t)row * Pp;

    float v0 = in[tid], v1 = in[tid + 256];
    float lmax = fmaxf(v0, v1);
#pragma unroll
    for (int o = 16; o > 0; o >>= 1)
        lmax = fmaxf(lmax, __shfl_xor_sync(0xffffffffu, lmax, o));
    if ((tid & 31) == 0) sred[tid >> 5] = lmax;
    __syncthreads();
    if (tid == 0) {
        float m = sred[0];
#pragma unroll
        for (int w = 1; w < 8; w++) m = fmaxf(m, sred[w]);
        sbc[0] = m;
    }
    __syncthreads();
    float smax = sbc[0];

    float e0 = __expf(v0 - smax), e1 = __expf(v1 - smax);
    float lsum = e0 + e1;
#pragma unroll
    for (int o = 16; o > 0; o >>= 1)
        lsum += __shfl_xor_sync(0xffffffffu, lsum, o);
    if ((tid & 31) == 0) sred[tid >> 5] = lsum;
    __syncthreads();
    if (tid == 0) {
        float s = 0.f;
#pragma unroll
        for (int w = 0; w < 8; w++) s += sred[w];
        sbc[1] = 1.f / s;
    }
    __syncthreads();
    float inv = sbc[1];
    out[(size_t)row * Pp + tid] = e0 * inv;
    out[(size_t)row * Pp + tid + 256] = e1 * inv;
}

// ---------------------------------------------------------------------------
extern "C" void kernel_launch(void* const* d_in, const int* in_sizes, int n_in,
                              void* d_out, int out_size) {
    const float* input1 = (const float*)d_in[0];
    const float* input2 = (const float*)d_in[1];
    const float* ctime  = (const float*)d_in[2];
    const float* mask   = (const float*)d_in[3];
    const float* enc    = (const float*)d_in[4];
    const float* Wq     = (const float*)d_in[5];
    const float* Wk     = (const float*)d_in[6];
    const float* Wv     = (const float*)d_in[7];
    const float* Wcw    = (const float*)d_in[8];
    const float* Wcb    = (const float*)d_in[9];
    float* out = (float*)d_out;

    qbias_kernel<<<Bb, 256>>>(input1, Wq);

    proj_kernel<<<dim3(64, 2, 3), 256>>>(enc, input2, Wk, Wv,
                                         Wq + Ee * HK, ctime, Wq + 2 * Ee * HK);

    cudaFuncSetAttribute(attn_kernel, cudaFuncAttributeMaxDynamicSharedMemorySize,
                         ATTN_SMEM_BYTES);
    attn_kernel<<<dim3(2, Hh, Bb), 256, ATTN_SMEM_BYTES>>>(mask);

    wc_kernel<<<dim3(64, 2), 256>>>(Wcw, Wcb);

    pointer_gemm<<<dim3(4, 4, Bb), 256>>>(enc, mask);

    softmax_kernel<<<Bb * Gg, 256>>>(out);
}